// round 13
// baseline (speedup 1.0000x reference)
#include <cuda_runtime.h>
#include <mma.h>

using namespace nvcuda;

#define NN 50000
#define DH 128
#define EMAX 600000

__device__ __align__(16) float g_h[(size_t)NN * DH];   // h = A @ W
__device__ __align__(16) float g_b[(size_t)NN * DH];   // layer-1 activation
__device__ __align__(16) float g_deg[NN];
__device__ __align__(16) float g_dinv[NN];
__device__ __align__(16) int   g_cnt[NN];
__device__ __align__(16) int   g_rowstart[NN + 1];
__device__ __align__(16) int   g_fill[NN];
__device__ __align__(16) int   g_csr_src[EMAX];
__device__ __align__(16) float g_csr_norm[EMAX];
__device__ int g_is64;

// ---------------- dtype probe ----------------

__global__ void probe_kernel(const int* __restrict__ ei32, int E) {
    __shared__ int any_nonzero;
    if (threadIdx.x == 0) any_nonzero = 0;
    __syncthreads();
    for (int i = threadIdx.x; i < 1024; i += blockDim.x) {
        int idx = 2 * i + 1;
        if (idx < 2 * E && ei32[idx] != 0) atomicOr(&any_nonzero, 1);
    }
    __syncthreads();
    if (threadIdx.x == 0) g_is64 = (any_nonzero == 0) ? 1 : 0;
}

// ---------------- prep ----------------

__global__ void zero_kernel(int n) {
    int i = blockIdx.x * blockDim.x + threadIdx.x;
    if (i < n) { g_deg[i] = 0.0f; g_cnt[i] = 0; }
}

__device__ __forceinline__ int load_edge_idx(const void* ei, size_t pos) {
    if (g_is64) return (int)((const long long*)ei)[pos];
    return ((const int*)ei)[pos];
}

__global__ void deg_kernel(const void* __restrict__ ei, const float* __restrict__ ew,
                           int E, int n) {
    int e = blockIdx.x * blockDim.x + threadIdx.x;
    if (e < E) {
        int d = load_edge_idx(ei, (size_t)E + e);
        if ((unsigned)d < (unsigned)n) {
            atomicAdd(&g_deg[d], ew[e]);
            atomicAdd(&g_cnt[d], 1);
        }
    }
}

__global__ void dinv_kernel(int n) {
    int i = blockIdx.x * blockDim.x + threadIdx.x;
    if (i < n) g_dinv[i] = rsqrtf(g_deg[i] + 1.0f);
}

__global__ __launch_bounds__(1024) void scan_kernel(int n) {
    __shared__ int partial[1024];
    int t = threadIdx.x;
    int ch = (n + 1023) / 1024;
    int start = t * ch;
    int sum = 0;
    for (int i = 0; i < ch; i++) {
        int idx = start + i;
        if (idx < n) sum += g_cnt[idx];
    }
    partial[t] = sum;
    __syncthreads();
    for (int off = 1; off < 1024; off <<= 1) {
        int v = (t >= off) ? partial[t - off] : 0;
        __syncthreads();
        partial[t] += v;
        __syncthreads();
    }
    int run = (t > 0) ? partial[t - 1] : 0;
    for (int i = 0; i < ch; i++) {
        int idx = start + i;
        if (idx < n) {
            g_rowstart[idx] = run;
            g_fill[idx] = run;
            run += g_cnt[idx];
        }
    }
    if (t == 1023) g_rowstart[n] = partial[1023];
}

__global__ void build_csr_kernel(const void* __restrict__ ei, const float* __restrict__ ew,
                                 int E, int n) {
    int e = blockIdx.x * blockDim.x + threadIdx.x;
    if (e < E) {
        int s = load_edge_idx(ei, e);
        int d = load_edge_idx(ei, (size_t)E + e);
        if ((unsigned)s < (unsigned)n && (unsigned)d < (unsigned)n) {
            int pos = atomicAdd(&g_fill[d], 1);
            g_csr_src[pos] = s;
            g_csr_norm[pos] = g_dinv[s] * ew[e] * g_dinv[d];
        }
    }
}

// ---------------- GEMM: g_h[n,128] = A[n,128] @ W[128,128] -----------------
// 3xTF32 split on tensor cores (wmma m16n16k8). Block = 128 rows, 8 warps,
// warp = 16x128 stripe. W staged in 64KB dynamic smem; A read from global.

__global__ __launch_bounds__(256) void gemm_tf32_kernel(
    const float* __restrict__ A_ext, const float* __restrict__ W,
    int n, int from_gb)
{
    extern __shared__ float Ws[];   // 128*128 floats = 64KB
    const float* A = from_gb ? (const float*)g_b : A_ext;

    int t = threadIdx.x;
#pragma unroll
    for (int i = 0; i < 16; i++) {
        int idx = t + i * 256;                    // float4 slots 0..4095
        ((float4*)Ws)[idx] = ((const float4*)W)[idx];
    }
    __syncthreads();

    int warp = t >> 5;
    int row0 = blockIdx.x * 128 + warp * 16;      // n % 16 == 0
    if (row0 >= n) return;

    wmma::fragment<wmma::accumulator, 16, 16, 8, float> acc[8];
#pragma unroll
    for (int i = 0; i < 8; i++) wmma::fill_fragment(acc[i], 0.0f);

    wmma::fragment<wmma::matrix_a, 16, 16, 8, wmma::precision::tf32, wmma::row_major> ah, al;
    wmma::fragment<wmma::matrix_b, 16, 16, 8, wmma::precision::tf32, wmma::row_major> bh, bl;

    for (int k = 0; k < 128; k += 8) {
        wmma::load_matrix_sync(ah, A + (size_t)row0 * 128 + k, 128);
#pragma unroll
        for (int i = 0; i < ah.num_elements; i++) {
            float x  = ah.x[i];
            float hi = wmma::__float_to_tf32(x);
            ah.x[i] = hi;
            al.x[i] = wmma::__float_to_tf32(x - hi);
        }
#pragma unroll
        for (int nt = 0; nt < 8; nt++) {
            wmma::load_matrix_sync(bh, Ws + k * 128 + nt * 16, 128);
#pragma unroll
            for (int i = 0; i < bh.num_elements; i++) {
                float x  = bh.x[i];
                float hi = wmma::__float_to_tf32(x);
                bh.x[i] = hi;
                bl.x[i] = wmma::__float_to_tf32(x - hi);
            }
            wmma::mma_sync(acc[nt], ah, bh, acc[nt]);
            wmma::mma_sync(acc[nt], al, bh, acc[nt]);
            wmma::mma_sync(acc[nt], ah, bl, acc[nt]);
        }
    }

#pragma unroll
    for (int nt = 0; nt < 8; nt++)
        wmma::store_matrix_sync(g_h + (size_t)row0 * 128 + nt * 16, acc[nt],
                                128, wmma::mem_row_major);
}

// ---------------- aggregate: warp per dst node, register accumulation ----------

__global__ __launch_bounds__(256) void agg_kernel(
    const float* __restrict__ bias, float* __restrict__ out_ext,
    int n, int to_gb, int do_relu)
{
    float* out = to_gb ? (float*)g_b : out_ext;
    int warp = (blockIdx.x * blockDim.x + threadIdx.x) >> 5;
    int lane = threadIdx.x & 31;
    if (warp >= n) return;

    float di = g_dinv[warp];
    float sl = di * di;
    float4 hv = *((const float4*)(g_h + (size_t)warp * 128) + lane);
    float4 bv = *((const float4*)bias + lane);
    float4 acc;
    acc.x = hv.x * sl + bv.x;
    acc.y = hv.y * sl + bv.y;
    acc.z = hv.z * sl + bv.z;
    acc.w = hv.w * sl + bv.w;

    int p  = g_rowstart[warp];
    int p1 = g_rowstart[warp + 1];

    for (; p + 3 < p1; p += 4) {
        int   s0 = g_csr_src[p],     s1 = g_csr_src[p + 1];
        int   s2 = g_csr_src[p + 2], s3 = g_csr_src[p + 3];
        float n0 = g_csr_norm[p],     n1 = g_csr_norm[p + 1];
        float n2 = g_csr_norm[p + 2], n3 = g_csr_norm[p + 3];
        float4 v0 = *((const float4*)(g_h + (size_t)s0 * 128) + lane);
        float4 v1 = *((const float4*)(g_h + (size_t)s1 * 128) + lane);
        float4 v2 = *((const float4*)(g_h + (size_t)s2 * 128) + lane);
        float4 v3 = *((const float4*)(g_h + (size_t)s3 * 128) + lane);
        acc.x += n0 * v0.x + n1 * v1.x + n2 * v2.x + n3 * v3.x;
        acc.y += n0 * v0.y + n1 * v1.y + n2 * v2.y + n3 * v3.y;
        acc.z += n0 * v0.z + n1 * v1.z + n2 * v2.z + n3 * v3.z;
        acc.w += n0 * v0.w + n1 * v1.w + n2 * v2.w + n3 * v3.w;
    }
    for (; p < p1; p++) {
        int   sa = g_csr_src[p];
        float na = g_csr_norm[p];
        float4 va = *((const float4*)(g_h + (size_t)sa * 128) + lane);
        acc.x += na * va.x;
        acc.y += na * va.y;
        acc.z += na * va.z;
        acc.w += na * va.w;
    }

    if (do_relu) {
        acc.x = fmaxf(acc.x, 0.f);
        acc.y = fmaxf(acc.y, 0.f);
        acc.z = fmaxf(acc.z, 0.f);
        acc.w = fmaxf(acc.w, 0.f);
    }
    *((float4*)(out + (size_t)warp * 128) + lane) = acc;
}

// ---------------- launch ----------------

extern "C" void kernel_launch(void* const* d_in, const int* in_sizes, int n_in,
                              void* d_out, int out_size) {
    const float* x  = (const float*)d_in[0];
    const void*  ei = d_in[1];
    const float* ew = (const float*)d_in[2];
    const float* W1 = (const float*)d_in[3];
    const float* b1 = (const float*)d_in[4];
    const float* W2 = (const float*)d_in[5];
    const float* b2 = (const float*)d_in[6];
    float*       out = (float*)d_out;

    int n = in_sizes[0] / 128;   // 50000
    int E = in_sizes[2];         // 600000

    const int B = 256;
    const int SMEM = 128 * 128 * sizeof(float);   // 64KB

    static int attr_done = 0;
    if (!attr_done) {
        cudaFuncSetAttribute(gemm_tf32_kernel,
                             cudaFuncAttributeMaxDynamicSharedMemorySize, SMEM);
        attr_done = 1;
    }

    probe_kernel<<<1, 256>>>((const int*)ei, E);
    zero_kernel<<<(n + B - 1) / B, B>>>(n);
    deg_kernel<<<(E + B - 1) / B, B>>>(ei, ew, E, n);
    dinv_kernel<<<(n + B - 1) / B, B>>>(n);
    scan_kernel<<<1, 1024>>>(n);
    build_csr_kernel<<<(E + B - 1) / B, B>>>(ei, ew, E, n);

    int gemm_blocks = (n + 127) / 128;
    int agg_blocks = (n * 32 + B - 1) / B;

    // layer 1: h = x@W1 ; g_b = relu(agg(h) + b1)
    gemm_tf32_kernel<<<gemm_blocks, 256, SMEM>>>(x, W1, n, 0);
    agg_kernel<<<agg_blocks, B>>>(b1, out, n, 1, 1);

    // layer 2: h = g_b@W2 ; out = agg(h) + b2
    gemm_tf32_kernel<<<gemm_blocks, 256, SMEM>>>(x, W2, n, 1);
    agg_kernel<<<agg_blocks, B>>>(b2, out, n, 0, 0);
}